// round 1
// baseline (speedup 1.0000x reference)
#include <cuda_runtime.h>

#define BB 4
#define N1 2048
#define N2 8192
#define CIN 64
#define COUT 128
#define NKP 15
#define NS 32
#define RADIUS2 0.01f
#define INV_EXTENT 25.0f   /* 1 / 0.04 */
#define CHUNK 1024

// scratch (allocation-free rule: __device__ globals)
__device__ float g_featT[BB * N2 * CIN];   // 8 MB: support features transposed [B][N2][C]
__device__ float g_tmp1[BB * N1 * CIN];    // 2 MB: pre-conv aggregated features [B][N1][C]
__device__ float g_sum[COUT];
__device__ float g_sumsq[COUT];

// ---------------------------------------------------------------------------
// k0: transpose support_features [B][C][N2] -> g_featT [B][N2][C]
// ---------------------------------------------------------------------------
__global__ void k_transpose(const float* __restrict__ f) {
    __shared__ float tile[32][33];
    int b = blockIdx.z;
    int c0 = blockIdx.y * 32, n0 = blockIdx.x * 32;
    int tx = threadIdx.x, ty = threadIdx.y;  // block (32, 8)
#pragma unroll
    for (int i = ty; i < 32; i += 8)
        tile[i][tx] = f[((b * CIN + c0 + i) * N2) + n0 + tx];
    __syncthreads();
#pragma unroll
    for (int i = ty; i < 32; i += 8)
        g_featT[((b * N2 + n0 + i) * CIN) + c0 + tx] = tile[tx][i];
}

// ---------------------------------------------------------------------------
// k1: ball query (ordered first-32) + kernel-point weighting + feature
//     aggregation. One warp per query, 8 queries per 256-thread block.
// ---------------------------------------------------------------------------
__global__ __launch_bounds__(256) void k_group(
    const float* __restrict__ qxyz, const float* __restrict__ sxyz,
    const float* __restrict__ qmask, const float* __restrict__ smask,
    const float* __restrict__ kp, const float* __restrict__ kw) {
    __shared__ float s_pos[CHUNK * 3];       // 12 KB support xyz chunk
    __shared__ float s_m[CHUNK];             // 4 KB support mask chunk
    __shared__ float4 s_nbr[8][NS];          // rel xyz + idx bits
    __shared__ float s_w[8][NS][NKP];        // per-neighbor kernel weights
    __shared__ int   s_ji[8][NS];            // effective neighbor index
    __shared__ float s_kw[NKP * CIN];        // kernel_weights [15][64]

    int b = blockIdx.y;
    int warp = threadIdx.x >> 5, lane = threadIdx.x & 31;
    int q = blockIdx.x * 8 + warp;

    for (int t = threadIdx.x; t < NKP * CIN; t += 256) s_kw[t] = kw[t];

    float qx = qxyz[(b * N1 + q) * 3 + 0];
    float qy = qxyz[(b * N1 + q) * 3 + 1];
    float qz = qxyz[(b * N1 + q) * 3 + 2];
    float qm = qmask[b * N1 + q];

    // ---- phase A: ordered ball query ----
    int cnt = 0;
    bool done = false;
    for (int c0 = 0; c0 < N2; c0 += CHUNK) {
        __syncthreads();
        for (int t = threadIdx.x; t < CHUNK * 3; t += 256)
            s_pos[t] = sxyz[(b * N2 + c0) * 3 + t];
        for (int t = threadIdx.x; t < CHUNK; t += 256)
            s_m[t] = smask[b * N2 + c0 + t];
        __syncthreads();
        if (!done) {
            for (int t0 = 0; t0 < CHUNK; t0 += 32) {
                int i = t0 + lane;
                float dx = s_pos[3 * i]     - qx;
                float dy = s_pos[3 * i + 1] - qy;
                float dz = s_pos[3 * i + 2] - qz;
                float d2 = dx * dx + dy * dy + dz * dz;
                bool valid = (d2 < RADIUS2) && (s_m[i] > 0.0f);
                unsigned bal = __ballot_sync(0xffffffffu, valid);
                if (bal) {
                    int slot = cnt + __popc(bal & ((1u << lane) - 1u));
                    if (valid && slot < NS)
                        s_nbr[warp][slot] =
                            make_float4(dx, dy, dz, __int_as_float(c0 + i));
                    cnt += __popc(bal);
                    if (cnt >= NS) { done = true; break; }
                }
            }
        }
    }
    __syncthreads();

    // ---- phase B: kernel-point influence weights (lane = neighbor slot) ----
    int cap = cnt < NS ? cnt : NS;
    float4 n0;
    if (cnt > 0) {
        n0 = s_nbr[warp][0];
    } else {
        n0 = make_float4(sxyz[b * N2 * 3]     - qx,
                         sxyz[b * N2 * 3 + 1] - qy,
                         sxyz[b * N2 * 3 + 2] - qz, __int_as_float(0));
    }
    int s = lane;
    float4 nb = (s < cap) ? s_nbr[warp][s] : n0;
    // feature_mask = nb_mask + (1 - query_mask)
    float fm = (s < cap) ? (2.0f - qm) : (1.0f - qm);
    s_ji[warp][s] = __float_as_int(nb.w);
#pragma unroll
    for (int k = 0; k < NKP; k++) {
        float dx = nb.x - kp[3 * k];
        float dy = nb.y - kp[3 * k + 1];
        float dz = nb.z - kp[3 * k + 2];
        float d = sqrtf(dx * dx + dy * dy + dz * dz);
        s_w[warp][s][k] = fmaxf(0.0f, 1.0f - d * INV_EXTENT) * fm;
    }
    __syncwarp();

    // ---- phase C: aggregate features (lane = channel pair) ----
    float acc0 = 0.f, acc1 = 0.f;
    int c_lo = lane, c_hi = lane + 32;
    for (int s2 = 0; s2 < NS; s2++) {
        int j = s_ji[warp][s2];
        const float* frow = g_featT + (size_t)(b * N2 + j) * CIN;
        float coef0 = 0.f, coef1 = 0.f;
#pragma unroll
        for (int k = 0; k < NKP; k++) {
            float w = s_w[warp][s2][k];
            coef0 += w * s_kw[k * CIN + c_lo];
            coef1 += w * s_kw[k * CIN + c_hi];
        }
        acc0 += coef0 * frow[c_lo];
        acc1 += coef1 * frow[c_hi];
    }
    g_tmp1[(size_t)(b * N1 + q) * CIN + c_lo] = acc0;
    g_tmp1[(size_t)(b * N1 + q) * CIN + c_hi] = acc1;
}

// ---------------------------------------------------------------------------
// k2a: zero BN accumulators
// ---------------------------------------------------------------------------
__global__ void k_init() {
    g_sum[threadIdx.x] = 0.0f;
    g_sumsq[threadIdx.x] = 0.0f;
}

// ---------------------------------------------------------------------------
// k2: 1x1 conv (W_out @ feats) + BN stat accumulation.
//     Block = 32 points x 128 out channels; warp w -> 16 channels, lane -> point.
// ---------------------------------------------------------------------------
__global__ __launch_bounds__(256) void k_gemm(const float* __restrict__ Wout,
                                              float* __restrict__ out) {
    __shared__ float s_f[32][65];        // 32 points x 64 channels (padded)
    __shared__ float s_w[COUT * CIN];    // 32 KB
    int p0 = blockIdx.x * 32;

    for (int t = threadIdx.x; t < COUT * CIN; t += 256) s_w[t] = Wout[t];
    for (int t = threadIdx.x; t < 32 * CIN; t += 256)
        s_f[t >> 6][t & 63] = g_tmp1[(size_t)p0 * CIN + t];
    __syncthreads();

    int warp = threadIdx.x >> 5, lane = threadIdx.x & 31;
    int o0 = warp * 16;
    int p = p0 + lane;
    float acc[16];
#pragma unroll
    for (int u = 0; u < 16; u++) acc[u] = 0.f;
#pragma unroll 4
    for (int c = 0; c < CIN; c++) {
        float f = s_f[lane][c];
#pragma unroll
        for (int u = 0; u < 16; u++) acc[u] += f * s_w[(o0 + u) * CIN + c];
    }

    int b = p >> 11;          // / N1
    int n = p & (N1 - 1);
#pragma unroll
    for (int u = 0; u < 16; u++) {
        float v = acc[u];
        out[(size_t)(b * COUT + o0 + u) * N1 + n] = v;
        float sv = v, sq = v * v;
#pragma unroll
        for (int off = 16; off; off >>= 1) {
            sv += __shfl_xor_sync(0xffffffffu, sv, off);
            sq += __shfl_xor_sync(0xffffffffu, sq, off);
        }
        if (lane == 0) {
            atomicAdd(&g_sum[o0 + u], sv);
            atomicAdd(&g_sumsq[o0 + u], sq);
        }
    }
}

// ---------------------------------------------------------------------------
// k3: BatchNorm (training-mode batch stats) + ReLU, in-place on d_out
// ---------------------------------------------------------------------------
__global__ void k_bn(float* __restrict__ out, const float* __restrict__ gamma,
                     const float* __restrict__ beta) {
    int i = blockIdx.x * 256 + threadIdx.x;  // B*COUT*N1 = 1,048,576
    int o = (i >> 11) & (COUT - 1);
    const float invM = 1.0f / (float)(BB * N1);
    float mean = g_sum[o] * invM;
    float var = g_sumsq[o] * invM - mean * mean;
    float inv = rsqrtf(var + 1e-5f);
    float v = (out[i] - mean) * inv * gamma[o] + beta[o];
    out[i] = fmaxf(v, 0.0f);
}

// ---------------------------------------------------------------------------
extern "C" void kernel_launch(void* const* d_in, const int* in_sizes, int n_in,
                              void* d_out, int out_size) {
    const float* qxyz  = (const float*)d_in[0];
    const float* sxyz  = (const float*)d_in[1];
    const float* qmask = (const float*)d_in[2];
    const float* smask = (const float*)d_in[3];
    const float* feats = (const float*)d_in[4];
    const float* kp    = (const float*)d_in[5];
    const float* kw    = (const float*)d_in[6];
    const float* Wout  = (const float*)d_in[7];
    const float* gamma = (const float*)d_in[8];
    const float* beta  = (const float*)d_in[9];
    float* out = (float*)d_out;

    k_transpose<<<dim3(N2 / 32, CIN / 32, BB), dim3(32, 8)>>>(feats);
    k_group<<<dim3(N1 / 8, BB), 256>>>(qxyz, sxyz, qmask, smask, kp, kw);
    k_init<<<1, COUT>>>();
    k_gemm<<<(BB * N1) / 32, 256>>>(Wout, out);
    k_bn<<<(BB * COUT * N1) / 256, 256>>>(out, gamma, beta);
}

// round 2
// speedup vs baseline: 1.3774x; 1.3774x over previous
#include <cuda_runtime.h>

#define BB 4
#define N1 2048
#define N2 8192
#define CIN 64
#define COUT 128
#define NKP 15
#define NS 32
#define RADIUS2 0.01f
#define INV_EXTENT 25.0f   /* 1 / 0.04 */
#define GRID 10
#define NCELL (GRID * GRID * GRID)
#define NCAND 128

// ---------------- scratch (__device__ globals: allocation-free rule) --------
__device__ float  g_featT[BB * N2 * CIN];     // 8 MB  [B][N2][C]
__device__ float  g_tmp1[BB * N1 * CIN];      // 2 MB  [B][N1][C]
__device__ float4 g_binned[BB * N2];          // points sorted by cell (x,y,z,jbits)
__device__ int    g_cellCnt[BB * NCELL];
__device__ int    g_cellStart[BB * NCELL];
__device__ int    g_cellOfs[BB * NCELL];
__device__ float  g_sum[COUT];
__device__ float  g_sumsq[COUT];

// ---------------- f32x2 helpers (FFMA2) -------------------------------------
__device__ __forceinline__ unsigned long long pack2(float a, float b) {
    unsigned long long r;
    asm("mov.b64 %0, {%1, %2};" : "=l"(r) : "f"(a), "f"(b));
    return r;
}
__device__ __forceinline__ unsigned long long fma2(unsigned long long a,
                                                   unsigned long long b,
                                                   unsigned long long c) {
    unsigned long long d;
    asm("fma.rn.f32x2 %0, %1, %2, %3;" : "=l"(d) : "l"(a), "l"(b), "l"(c));
    return d;
}
__device__ __forceinline__ void unpack2(unsigned long long v, float& a, float& b) {
    asm("mov.b64 {%0, %1}, %2;" : "=f"(a), "=f"(b) : "l"(v));
}

__device__ __forceinline__ int cell1d(float x) {
    int c = (int)(x * (float)GRID);
    return c < 0 ? 0 : (c > GRID - 1 ? GRID - 1 : c);
}

// ---------------------------------------------------------------------------
// k0: transpose support_features [B][C][N2] -> g_featT [B][N2][C]
// ---------------------------------------------------------------------------
__global__ void k_transpose(const float* __restrict__ f) {
    __shared__ float tile[32][33];
    int b = blockIdx.z;
    int c0 = blockIdx.y * 32, n0 = blockIdx.x * 32;
    int tx = threadIdx.x, ty = threadIdx.y;  // block (32, 8)
#pragma unroll
    for (int i = ty; i < 32; i += 8)
        tile[i][tx] = f[((b * CIN + c0 + i) * N2) + n0 + tx];
    __syncthreads();
#pragma unroll
    for (int i = ty; i < 32; i += 8)
        g_featT[((b * N2 + n0 + i) * CIN) + c0 + tx] = tile[tx][i];
}

// ---------------------------------------------------------------------------
// binning: zero counters + BN accumulators
// ---------------------------------------------------------------------------
__global__ void k_zero() {
    int i = blockIdx.x * 256 + threadIdx.x;
    if (i < BB * NCELL) g_cellCnt[i] = 0;
    if (i < COUT) { g_sum[i] = 0.0f; g_sumsq[i] = 0.0f; }
}

__global__ void k_hist(const float* __restrict__ sxyz,
                       const float* __restrict__ smask) {
    int p = blockIdx.x * 256 + threadIdx.x;  // BB*N2
    int b = p / N2, j = p % N2;
    if (smask[p] <= 0.0f) return;  // masked points never selectable
    float x = sxyz[p * 3], y = sxyz[p * 3 + 1], z = sxyz[p * 3 + 2];
    int cid = (cell1d(x) * GRID + cell1d(y)) * GRID + cell1d(z);
    atomicAdd(&g_cellCnt[b * NCELL + cid], 1);
    (void)j;
}

__global__ void k_scan() {  // one block per batch, 1024 threads
    __shared__ int s[1024];
    int b = blockIdx.x, t = threadIdx.x;
    int v = (t < NCELL) ? g_cellCnt[b * NCELL + t] : 0;
    s[t] = v;
    __syncthreads();
    for (int off = 1; off < 1024; off <<= 1) {
        int x = (t >= off) ? s[t - off] : 0;
        __syncthreads();
        s[t] += x;
        __syncthreads();
    }
    if (t < NCELL) {
        int start = s[t] - v;
        g_cellStart[b * NCELL + t] = start;
        g_cellOfs[b * NCELL + t] = start;
    }
}

__global__ void k_scatter(const float* __restrict__ sxyz,
                          const float* __restrict__ smask) {
    int p = blockIdx.x * 256 + threadIdx.x;  // BB*N2
    int b = p / N2, j = p % N2;
    if (smask[p] <= 0.0f) return;
    float x = sxyz[p * 3], y = sxyz[p * 3 + 1], z = sxyz[p * 3 + 2];
    int cid = (cell1d(x) * GRID + cell1d(y)) * GRID + cell1d(z);
    int pos = atomicAdd(&g_cellOfs[b * NCELL + cid], 1);
    g_binned[b * N2 + pos] = make_float4(x, y, z, __int_as_float(j));
}

// ---------------------------------------------------------------------------
// k1: grid-hashed ordered ball query + kernel-point weighting + aggregation.
//     One warp per query; 8 queries per 256-thread block.
// ---------------------------------------------------------------------------
__global__ __launch_bounds__(256) void k_group(
    const float* __restrict__ qxyz, const float* __restrict__ qmask,
    const float* __restrict__ kp, const float* __restrict__ kw) {
    __shared__ float4 s_cand[8][NCAND];                 // 16 KB rel xyz + jbits
    __shared__ unsigned s_key[8][NCAND];                // 4 KB
    __shared__ unsigned long long s_w2[8][NS][16];      // 32 KB  {w,w} pairs
    __shared__ int s_ji[8][NS];                         // 1 KB

    int b = blockIdx.y;
    int warp = threadIdx.x >> 5, lane = threadIdx.x & 31;
    int q = blockIdx.x * 8 + warp;
    unsigned lmask = (1u << lane) - 1u;

    float qx = qxyz[(b * N1 + q) * 3 + 0];
    float qy = qxyz[(b * N1 + q) * 3 + 1];
    float qz = qxyz[(b * N1 + q) * 3 + 2];
    float qm = qmask[b * N1 + q];

    // ---- phase A: candidate collection over 27 neighboring cells ----
    int cx = cell1d(qx), cy = cell1d(qy), cz = cell1d(qz);
    int x0 = cx > 0 ? cx - 1 : 0, x1 = cx < GRID - 1 ? cx + 1 : GRID - 1;
    int y0 = cy > 0 ? cy - 1 : 0, y1 = cy < GRID - 1 ? cy + 1 : GRID - 1;
    int z0 = cz > 0 ? cz - 1 : 0, z1 = cz < GRID - 1 ? cz + 1 : GRID - 1;

    int cnt = 0;
    for (int ix = x0; ix <= x1; ix++)
        for (int iy = y0; iy <= y1; iy++)
            for (int iz = z0; iz <= z1; iz++) {
                int cid = b * NCELL + (ix * GRID + iy) * GRID + iz;
                int s0 = g_cellStart[cid];
                int n = g_cellCnt[cid];
                for (int i0 = 0; i0 < n; i0 += 32) {
                    int i = i0 + lane;
                    bool valid = false;
                    float rx = 0.f, ry = 0.f, rz = 0.f;
                    int j = 0;
                    if (i < n) {
                        float4 p = g_binned[b * N2 + s0 + i];
                        rx = p.x - qx; ry = p.y - qy; rz = p.z - qz;
                        float d2 = rx * rx + ry * ry + rz * rz;
                        j = __float_as_int(p.w);
                        valid = d2 < RADIUS2;
                    }
                    unsigned bal = __ballot_sync(0xffffffffu, valid);
                    int slot = cnt + __popc(bal & lmask);
                    if (valid && slot < NCAND) {
                        s_cand[warp][slot] = make_float4(rx, ry, rz, __int_as_float(j));
                        s_key[warp][slot] = ((unsigned)j << 7) | (unsigned)slot;
                    }
                    cnt += __popc(bal);
                }
            }
    __syncwarp();

    // ---- in-warp bitonic sort of 128 keys (4 per lane), ascending by j ----
    int m = cnt < NCAND ? cnt : NCAND;
    unsigned v[4];
#pragma unroll
    for (int r = 0; r < 4; r++) {
        int idx = r * 32 + lane;
        v[r] = (idx < m) ? s_key[warp][idx] : 0xFFFFFFFFu;
    }
#pragma unroll
    for (int k = 2; k <= NCAND; k <<= 1) {
#pragma unroll
        for (int d = k >> 1; d > 0; d >>= 1) {
            if (d >= 32) {
                int rd = d >> 5;
#pragma unroll
                for (int r = 0; r < 4; r++) {
                    if ((r & rd) == 0) {
                        int r2 = r + rd;
                        bool asc = (((r * 32) & k) == 0);
                        unsigned a = v[r], bb = v[r2];
                        unsigned mn = a < bb ? a : bb;
                        unsigned mx = a < bb ? bb : a;
                        v[r] = asc ? mn : mx;
                        v[r2] = asc ? mx : mn;
                    }
                }
            } else {
#pragma unroll
                for (int r = 0; r < 4; r++) {
                    unsigned p = __shfl_xor_sync(0xffffffffu, v[r], d);
                    int idx = r * 32 + lane;
                    bool asc = ((idx & k) == 0);
                    bool lower = ((lane & d) == 0);
                    unsigned mn = v[r] < p ? v[r] : p;
                    unsigned mx = v[r] < p ? p : v[r];
                    v[r] = (lower == asc) ? mn : mx;
                }
            }
        }
    }

    // ---- phase B: first-32 selection + kernel-point influence weights ----
    int cap = cnt < NS ? cnt : NS;
    unsigned key0 = __shfl_sync(0xffffffffu, v[0], 0);  // smallest-j candidate
    float4 nb;
    int j;
    if (cap == 0) {
        nb = make_float4(0.f, 0.f, 0.f, 0.f);
        j = 0;  // weights all zero below; index just needs to be in-bounds
    } else {
        unsigned key = (lane < cap) ? v[0] : key0;
        nb = s_cand[warp][key & 127u];
        j = (int)(key >> 7);
    }
    float fm = (lane < cap) ? (2.0f - qm) : (1.0f - qm);
    if (cap == 0) fm = 0.0f;  // matches reference: nb_mask=0 & qmask handling
    else if (lane >= cap) fm = 1.0f - qm;
    s_ji[warp][lane] = j;
#pragma unroll
    for (int k = 0; k < NKP; k++) {
        float dx = nb.x - kp[3 * k];
        float dy = nb.y - kp[3 * k + 1];
        float dz = nb.z - kp[3 * k + 2];
        float d = sqrtf(dx * dx + dy * dy + dz * dz);
        float w = fmaxf(0.0f, 1.0f - d * INV_EXTENT) * fm;
        s_w2[warp][lane][k] = pack2(w, w);
    }
    __syncwarp();

    // ---- phase C: einsum over neighbors, FFMA2 on channel pairs ----
    unsigned long long kwp[NKP];
#pragma unroll
    for (int k = 0; k < NKP; k++)
        kwp[k] = *(const unsigned long long*)(kw + k * CIN + 2 * lane);

    unsigned long long acc = 0ULL;  // (0.0f, 0.0f)
#pragma unroll 4
    for (int s2 = 0; s2 < NS; s2++) {
        int jj = s_ji[warp][s2];
        unsigned long long f =
            *(const unsigned long long*)(g_featT + (size_t)(b * N2 + jj) * CIN + 2 * lane);
        unsigned long long cp = 0ULL;
#pragma unroll
        for (int k = 0; k < NKP; k++)
            cp = fma2(s_w2[warp][s2][k], kwp[k], cp);
        acc = fma2(cp, f, acc);
    }
    *(unsigned long long*)(g_tmp1 + (size_t)(b * N1 + q) * CIN + 2 * lane) = acc;
}

// ---------------------------------------------------------------------------
// k2: 1x1 conv (W_out @ feats) + BN stat accumulation.
//     Block = 64 points x 128 outs; thread = 4 points x 8 outs.
// ---------------------------------------------------------------------------
__global__ __launch_bounds__(256) void k_gemm(const float* __restrict__ Wout,
                                              float* __restrict__ out) {
    __shared__ float s_f[CIN][68];    // [c][point], 16B-aligned rows
    __shared__ float s_w[CIN][132];   // [c][out],   16B-aligned rows
    int p0 = blockIdx.x * 64;
    int t = threadIdx.x;

    // stage feats transposed: g_tmp1 [p][c] -> s_f[c][p]
    for (int e = t; e < 64 * CIN; e += 256) {
        int p = e >> 6, c = e & 63;
        s_f[c][p] = g_tmp1[(size_t)(p0 + p) * CIN + c];
    }
    // stage weights transposed: Wout [o][c] -> s_w[c][o]
    for (int e = t; e < COUT * CIN; e += 256) {
        int o = e >> 6, c = e & 63;
        s_w[c][o] = Wout[e];
    }
    __syncthreads();

    int pg = t & 15;        // 16 point-groups of 4
    int og = t >> 4;        // 16 out-groups of 8
    float acc[8][4];
#pragma unroll
    for (int o = 0; o < 8; o++)
#pragma unroll
        for (int p = 0; p < 4; p++) acc[o][p] = 0.f;

#pragma unroll 4
    for (int c = 0; c < CIN; c++) {
        float4 f = *(const float4*)&s_f[c][pg * 4];
        float4 w0 = *(const float4*)&s_w[c][og * 8];
        float4 w1 = *(const float4*)&s_w[c][og * 8 + 4];
        float wv[8] = {w0.x, w0.y, w0.z, w0.w, w1.x, w1.y, w1.z, w1.w};
        float fv[4] = {f.x, f.y, f.z, f.w};
#pragma unroll
        for (int o = 0; o < 8; o++)
#pragma unroll
            for (int p = 0; p < 4; p++) acc[o][p] += wv[o] * fv[p];
    }

    int pglob = p0 + pg * 4;
    int b = pglob >> 11;
    int n = pglob & (N1 - 1);
#pragma unroll
    for (int o = 0; o < 8; o++) {
        int oc = og * 8 + o;
        *(float4*)&out[(size_t)(b * COUT + oc) * N1 + n] =
            make_float4(acc[o][0], acc[o][1], acc[o][2], acc[o][3]);
        float sv = acc[o][0] + acc[o][1] + acc[o][2] + acc[o][3];
        float sq = acc[o][0] * acc[o][0] + acc[o][1] * acc[o][1] +
                   acc[o][2] * acc[o][2] + acc[o][3] * acc[o][3];
#pragma unroll
        for (int off = 8; off; off >>= 1) {  // reduce over the 16-lane group
            sv += __shfl_xor_sync(0xffffffffu, sv, off);
            sq += __shfl_xor_sync(0xffffffffu, sq, off);
        }
        if ((t & 15) == 0) {
            atomicAdd(&g_sum[oc], sv);
            atomicAdd(&g_sumsq[oc], sq);
        }
    }
}

// ---------------------------------------------------------------------------
// k3: BatchNorm (training-mode batch stats) + ReLU, in-place on d_out
// ---------------------------------------------------------------------------
__global__ void k_bn(float* __restrict__ out, const float* __restrict__ gamma,
                     const float* __restrict__ beta) {
    int i = blockIdx.x * 256 + threadIdx.x;  // B*COUT*N1
    int o = (i >> 11) & (COUT - 1);
    const float invM = 1.0f / (float)(BB * N1);
    float mean = g_sum[o] * invM;
    float var = g_sumsq[o] * invM - mean * mean;
    float inv = rsqrtf(var + 1e-5f);
    float v = (out[i] - mean) * inv * gamma[o] + beta[o];
    out[i] = fmaxf(v, 0.0f);
}

// ---------------------------------------------------------------------------
extern "C" void kernel_launch(void* const* d_in, const int* in_sizes, int n_in,
                              void* d_out, int out_size) {
    const float* qxyz  = (const float*)d_in[0];
    const float* sxyz  = (const float*)d_in[1];
    const float* qmask = (const float*)d_in[2];
    const float* smask = (const float*)d_in[3];
    const float* feats = (const float*)d_in[4];
    const float* kp    = (const float*)d_in[5];
    const float* kw    = (const float*)d_in[6];
    const float* Wout  = (const float*)d_in[7];
    const float* gamma = (const float*)d_in[8];
    const float* beta  = (const float*)d_in[9];
    float* out = (float*)d_out;

    k_transpose<<<dim3(N2 / 32, CIN / 32, BB), dim3(32, 8)>>>(feats);
    k_zero<<<(BB * NCELL + 255) / 256, 256>>>();
    k_hist<<<(BB * N2) / 256, 256>>>(sxyz, smask);
    k_scan<<<BB, 1024>>>();
    k_scatter<<<(BB * N2) / 256, 256>>>(sxyz, smask);
    k_group<<<dim3(N1 / 8, BB), 256>>>(qxyz, qmask, kp, kw);
    k_gemm<<<(BB * N1) / 64, 256>>>(Wout, out);
    k_bn<<<(BB * COUT * N1) / 256, 256>>>(out, gamma, beta);
}

// round 3
// speedup vs baseline: 2.1161x; 1.5362x over previous
#include <cuda_runtime.h>

#define BB 4
#define N1 2048
#define N2 8192
#define CIN 64
#define COUT 128
#define NKP 15
#define NS 32
#define RADIUS2 0.01f
#define INV_EXTENT 25.0f   /* 1 / 0.04 */
#define GRID 10
#define NCELL (GRID * GRID * GRID)
#define NCAND 128

// ---------------- scratch (__device__ globals: allocation-free rule) --------
__device__ float  g_featT[BB * N2 * CIN];        // 8 MB  [B][N2][C]
__device__ float  g_tmp1[BB * N1 * CIN];         // 2 MB  [B][N1][C]
__device__ float4 g_binned[BB * N2];             // points grouped by cell
__device__ int    g_cellStart[BB * (NCELL + 1)]; // cumulative starts per batch
__device__ float  g_sum[COUT];
__device__ float  g_sumsq[COUT];

// ---------------- f32x2 helpers (FFMA2) -------------------------------------
__device__ __forceinline__ unsigned long long pack2(float a, float b) {
    unsigned long long r;
    asm("mov.b64 %0, {%1, %2};" : "=l"(r) : "f"(a), "f"(b));
    return r;
}
__device__ __forceinline__ unsigned long long fma2(unsigned long long a,
                                                   unsigned long long b,
                                                   unsigned long long c) {
    unsigned long long d;
    asm("fma.rn.f32x2 %0, %1, %2, %3;" : "=l"(d) : "l"(a), "l"(b), "l"(c));
    return d;
}

__device__ __forceinline__ int cell1d(float x) {
    int c = (int)(x * (float)GRID);
    return c < 0 ? 0 : (c > GRID - 1 ? GRID - 1 : c);
}

// ---------------------------------------------------------------------------
// k_prep: blocks 0..3  -> per-batch binning (hist + scan + scatter in SMEM)
//         blocks 4..   -> transpose support_features [B][C][N2] -> [B][N2][C]
// ---------------------------------------------------------------------------
__global__ __launch_bounds__(1024) void k_prep(const float* __restrict__ f,
                                               const float* __restrict__ sxyz,
                                               const float* __restrict__ smask) {
    __shared__ float tile[32][33];
    __shared__ int s_cnt[NCELL];
    __shared__ int s_wsum[32];

    int t = threadIdx.x;

    if (blockIdx.x < BB) {
        // ================= binning block for batch b =================
        int b = blockIdx.x;
        if (b == 0 && t < COUT) { g_sum[t] = 0.0f; g_sumsq[t] = 0.0f; }

        if (t < NCELL) s_cnt[t] = 0;
        __syncthreads();

        float px[8], py[8], pz[8];
        int pc[8];
#pragma unroll
        for (int i = 0; i < 8; i++) {
            int j = i * 1024 + t;
            int p = b * N2 + j;
            float x = sxyz[p * 3], y = sxyz[p * 3 + 1], z = sxyz[p * 3 + 2];
            px[i] = x; py[i] = y; pz[i] = z;
            if (smask[p] > 0.0f) {
                int cid = (cell1d(x) * GRID + cell1d(y)) * GRID + cell1d(z);
                pc[i] = cid;
                atomicAdd(&s_cnt[cid], 1);
            } else {
                pc[i] = -1;
            }
        }
        __syncthreads();

        // exclusive scan of s_cnt[0..NCELL) using warp shuffles
        int lane = t & 31, w = t >> 5;
        int v = (t < NCELL) ? s_cnt[t] : 0;
        int incl = v;
#pragma unroll
        for (int o = 1; o < 32; o <<= 1) {
            int n = __shfl_up_sync(0xffffffffu, incl, o);
            if (lane >= o) incl += n;
        }
        if (lane == 31) s_wsum[w] = incl;
        __syncthreads();
        if (w == 0) {
            int sv = s_wsum[lane];
            int si = sv;
#pragma unroll
            for (int o = 1; o < 32; o <<= 1) {
                int n = __shfl_up_sync(0xffffffffu, si, o);
                if (lane >= o) si += n;
            }
            s_wsum[lane] = si - sv;  // exclusive warp offset
        }
        __syncthreads();
        int total_incl = incl + s_wsum[w];
        int start = total_incl - v;
        __syncthreads();  // everyone done reading s_wsum / s_cnt
        if (t < NCELL) {
            g_cellStart[b * (NCELL + 1) + t] = start;
            if (t == NCELL - 1) g_cellStart[b * (NCELL + 1) + NCELL] = total_incl;
            s_cnt[t] = start;  // running offsets for scatter
        }
        __syncthreads();

#pragma unroll
        for (int i = 0; i < 8; i++) {
            if (pc[i] >= 0) {
                int pos = atomicAdd(&s_cnt[pc[i]], 1);
                g_binned[b * N2 + pos] =
                    make_float4(px[i], py[i], pz[i], __int_as_float(i * 1024 + t));
            }
        }
    } else {
        // ================= transpose tile =================
        int tb = blockIdx.x - BB;               // 0 .. 2047
        int n0 = (tb & 255) * 32;               // N2/32 = 256 tiles
        int c0 = ((tb >> 8) & 1) * 32;          // CIN/32 = 2
        int b = tb >> 9;
        int tx = t & 31, ty = t >> 5;
        tile[ty][tx] = f[((b * CIN + c0 + ty) * N2) + n0 + tx];
        __syncthreads();
        g_featT[((b * N2 + n0 + ty) * CIN) + c0 + tx] = tile[tx][ty];
    }
}

// ---------------------------------------------------------------------------
// k_group: grid-hashed ordered ball query + kernel-point weighting +
//          aggregation. One warp per query; 8 queries per 256-thread block.
// ---------------------------------------------------------------------------
__global__ __launch_bounds__(256) void k_group(
    const float* __restrict__ qxyz, const float* __restrict__ qmask,
    const float* __restrict__ sxyz,
    const float* __restrict__ kp, const float* __restrict__ kw) {
    __shared__ float4 s_cand[8][NCAND];                 // 16 KB rel xyz + jbits
    __shared__ unsigned s_key[8][NCAND];                // 4 KB
    __shared__ unsigned long long s_w2[8][NS][NKP];     // 30 KB {w,w} pairs
    __shared__ int s_ji[8][NS];                         // 1 KB

    int b = blockIdx.y;
    int warp = threadIdx.x >> 5, lane = threadIdx.x & 31;
    int q = blockIdx.x * 8 + warp;
    unsigned lmask = (1u << lane) - 1u;
    const unsigned FULL = 0xffffffffu;

    float qx = qxyz[(b * N1 + q) * 3 + 0];
    float qy = qxyz[(b * N1 + q) * 3 + 1];
    float qz = qxyz[(b * N1 + q) * 3 + 2];
    float qm = qmask[b * N1 + q];

    // ---- phase A: flattened candidate scan over 9 z-contiguous segments ----
    int cx = cell1d(qx), cy = cell1d(qy), cz = cell1d(qz);
    int z0 = cz > 0 ? cz - 1 : 0, z1 = cz < GRID - 1 ? cz + 1 : GRID - 1;

    const int* cs = g_cellStart + b * (NCELL + 1);
    int seg_s0 = 0, seg_len = 0;
    if (lane < 9) {
        int ix = cx + lane / 3 - 1;
        int iy = cy + lane % 3 - 1;
        if (ix >= 0 && ix < GRID && iy >= 0 && iy < GRID) {
            int cbase = (ix * GRID + iy) * GRID;
            seg_s0 = cs[cbase + z0];
            seg_len = cs[cbase + z1 + 1] - seg_s0;
        }
    }
    // inclusive scan of seg_len over lanes
    int cum = seg_len;
#pragma unroll
    for (int o = 1; o < 16; o <<= 1) {
        int n = __shfl_up_sync(FULL, cum, o);
        if (lane >= o) cum += n;
    }
    int T = __shfl_sync(FULL, cum, 8);
    // broadcast all 9 (cum, s0) to every lane
    int cumk[9], s0k[9];
#pragma unroll
    for (int k = 0; k < 9; k++) {
        cumk[k] = __shfl_sync(FULL, cum, k);
        s0k[k] = __shfl_sync(FULL, seg_s0, k);
    }

    int cnt = 0;
    for (int t0 = 0; t0 < T; t0 += 32) {
        int g = t0 + lane;
        bool inb = g < T;
        // map g -> binned address via select chain over segments
        int addr = s0k[0] + g;
#pragma unroll
        for (int k = 1; k < 9; k++)
            if (g >= cumk[k - 1]) addr = s0k[k] + (g - cumk[k - 1]);
        if (!inb) addr = 0;
        float4 p = g_binned[b * N2 + addr];
        float rx = p.x - qx, ry = p.y - qy, rz = p.z - qz;
        float d2 = rx * rx + ry * ry + rz * rz;
        bool valid = inb && (d2 < RADIUS2);
        unsigned bal = __ballot_sync(FULL, valid);
        int slot = cnt + __popc(bal & lmask);
        if (valid && slot < NCAND) {
            s_cand[warp][slot] = make_float4(rx, ry, rz, p.w);
            s_key[warp][slot] =
                ((unsigned)__float_as_int(p.w) << 7) | (unsigned)slot;
        }
        cnt += __popc(bal);
    }
    __syncwarp();

    // ---- in-warp bitonic sort of 128 keys (4/lane), ascending by j ----
    int m = cnt < NCAND ? cnt : NCAND;
    unsigned v[4];
#pragma unroll
    for (int r = 0; r < 4; r++) {
        int idx = r * 32 + lane;
        v[r] = (idx < m) ? s_key[warp][idx] : 0xFFFFFFFFu;
    }
#pragma unroll
    for (int k = 2; k <= NCAND; k <<= 1) {
#pragma unroll
        for (int d = k >> 1; d > 0; d >>= 1) {
            if (d >= 32) {
                int rd = d >> 5;
#pragma unroll
                for (int r = 0; r < 4; r++) {
                    if ((r & rd) == 0) {
                        int r2 = r + rd;
                        bool asc = (((r * 32) & k) == 0);
                        unsigned a = v[r], bb2 = v[r2];
                        unsigned mn = a < bb2 ? a : bb2;
                        unsigned mx = a < bb2 ? bb2 : a;
                        v[r] = asc ? mn : mx;
                        v[r2] = asc ? mx : mn;
                    }
                }
            } else {
#pragma unroll
                for (int r = 0; r < 4; r++) {
                    unsigned p = __shfl_xor_sync(FULL, v[r], d);
                    int idx = r * 32 + lane;
                    bool asc = ((idx & k) == 0);
                    bool lower = ((lane & d) == 0);
                    unsigned mn = v[r] < p ? v[r] : p;
                    unsigned mx = v[r] < p ? p : v[r];
                    v[r] = (lower == asc) ? mn : mx;
                }
            }
        }
    }

    // ---- phase B: first-32 selection + kernel-point influence weights ----
    int cap = cnt < NS ? cnt : NS;
    unsigned key0 = __shfl_sync(FULL, v[0], 0);  // smallest-j candidate
    float4 nb;
    int j;
    float fm;
    if (cap == 0) {
        // reference pads idx with 0 -> rel pos of support point 0, nb_mask=0
        nb = make_float4(sxyz[b * N2 * 3] - qx, sxyz[b * N2 * 3 + 1] - qy,
                         sxyz[b * N2 * 3 + 2] - qz, 0.0f);
        j = 0;
        fm = 1.0f - qm;
    } else {
        unsigned key = (lane < cap) ? v[0] : key0;
        nb = s_cand[warp][key & 127u];
        j = (int)(key >> 7);
        fm = (lane < cap) ? (2.0f - qm) : (1.0f - qm);
    }
    s_ji[warp][lane] = j;
#pragma unroll
    for (int k = 0; k < NKP; k++) {
        float dx = nb.x - kp[3 * k];
        float dy = nb.y - kp[3 * k + 1];
        float dz = nb.z - kp[3 * k + 2];
        float d = sqrtf(dx * dx + dy * dy + dz * dz);
        float w = fmaxf(0.0f, 1.0f - d * INV_EXTENT) * fm;
        s_w2[warp][lane][k] = pack2(w, w);
    }
    __syncwarp();

    // ---- phase C: einsum over neighbors, FFMA2 on channel pairs ----
    unsigned long long kwp[NKP];
#pragma unroll
    for (int k = 0; k < NKP; k++)
        kwp[k] = *(const unsigned long long*)(kw + k * CIN + 2 * lane);

    unsigned long long acc = 0ULL;
#pragma unroll 4
    for (int s2 = 0; s2 < NS; s2++) {
        int jj = s_ji[warp][s2];
        unsigned long long fch =
            *(const unsigned long long*)(g_featT + (size_t)(b * N2 + jj) * CIN + 2 * lane);
        unsigned long long cp = 0ULL;
#pragma unroll
        for (int k = 0; k < NKP; k++)
            cp = fma2(s_w2[warp][s2][k], kwp[k], cp);
        acc = fma2(cp, fch, acc);
    }
    *(unsigned long long*)(g_tmp1 + (size_t)(b * N1 + q) * CIN + 2 * lane) = acc;
}

// ---------------------------------------------------------------------------
// k_gemm: 1x1 conv (W_out @ feats) + BN stat accumulation.
//         Block = 64 points x 128 outs; thread = 4 points x 8 outs.
// ---------------------------------------------------------------------------
__global__ __launch_bounds__(256) void k_gemm(const float* __restrict__ Wout,
                                              float* __restrict__ out) {
    __shared__ float s_f[CIN][68];    // [c][point]
    __shared__ float s_w[CIN][132];   // [c][out]
    int p0 = blockIdx.x * 64;
    int t = threadIdx.x;

    for (int e = t; e < 64 * CIN; e += 256) {
        int p = e >> 6, c = e & 63;
        s_f[c][p] = g_tmp1[(size_t)(p0 + p) * CIN + c];
    }
    for (int e = t; e < COUT * CIN; e += 256) {
        int o = e >> 6, c = e & 63;
        s_w[c][o] = Wout[e];
    }
    __syncthreads();

    int pg = t & 15;
    int og = t >> 4;
    float acc[8][4];
#pragma unroll
    for (int o = 0; o < 8; o++)
#pragma unroll
        for (int p = 0; p < 4; p++) acc[o][p] = 0.f;

#pragma unroll 4
    for (int c = 0; c < CIN; c++) {
        float4 fv4 = *(const float4*)&s_f[c][pg * 4];
        float4 w0 = *(const float4*)&s_w[c][og * 8];
        float4 w1 = *(const float4*)&s_w[c][og * 8 + 4];
        float wv[8] = {w0.x, w0.y, w0.z, w0.w, w1.x, w1.y, w1.z, w1.w};
        float fv[4] = {fv4.x, fv4.y, fv4.z, fv4.w};
#pragma unroll
        for (int o = 0; o < 8; o++)
#pragma unroll
            for (int p = 0; p < 4; p++) acc[o][p] += wv[o] * fv[p];
    }

    int pglob = p0 + pg * 4;
    int b = pglob >> 11;
    int n = pglob & (N1 - 1);
#pragma unroll
    for (int o = 0; o < 8; o++) {
        int oc = og * 8 + o;
        *(float4*)&out[(size_t)(b * COUT + oc) * N1 + n] =
            make_float4(acc[o][0], acc[o][1], acc[o][2], acc[o][3]);
        float sv = acc[o][0] + acc[o][1] + acc[o][2] + acc[o][3];
        float sq = acc[o][0] * acc[o][0] + acc[o][1] * acc[o][1] +
                   acc[o][2] * acc[o][2] + acc[o][3] * acc[o][3];
#pragma unroll
        for (int off = 8; off; off >>= 1) {
            sv += __shfl_xor_sync(0xffffffffu, sv, off);
            sq += __shfl_xor_sync(0xffffffffu, sq, off);
        }
        if ((t & 15) == 0) {
            atomicAdd(&g_sum[oc], sv);
            atomicAdd(&g_sumsq[oc], sq);
        }
    }
}

// ---------------------------------------------------------------------------
// k_bn: BatchNorm (training-mode batch stats) + ReLU, in-place on d_out
// ---------------------------------------------------------------------------
__global__ void k_bn(float* __restrict__ out, const float* __restrict__ gamma,
                     const float* __restrict__ beta) {
    int i = blockIdx.x * 256 + threadIdx.x;
    int o = (i >> 11) & (COUT - 1);
    const float invM = 1.0f / (float)(BB * N1);
    float mean = g_sum[o] * invM;
    float var = g_sumsq[o] * invM - mean * mean;
    float inv = rsqrtf(var + 1e-5f);
    float v = (out[i] - mean) * inv * gamma[o] + beta[o];
    out[i] = fmaxf(v, 0.0f);
}

// ---------------------------------------------------------------------------
extern "C" void kernel_launch(void* const* d_in, const int* in_sizes, int n_in,
                              void* d_out, int out_size) {
    const float* qxyz  = (const float*)d_in[0];
    const float* sxyz  = (const float*)d_in[1];
    const float* qmask = (const float*)d_in[2];
    const float* smask = (const float*)d_in[3];
    const float* feats = (const float*)d_in[4];
    const float* kp    = (const float*)d_in[5];
    const float* kw    = (const float*)d_in[6];
    const float* Wout  = (const float*)d_in[7];
    const float* gamma = (const float*)d_in[8];
    const float* beta  = (const float*)d_in[9];
    float* out = (float*)d_out;

    k_prep<<<BB + (N2 / 32) * (CIN / 32) * BB, 1024>>>(feats, sxyz, smask);
    k_group<<<dim3(N1 / 8, BB), 256>>>(qxyz, qmask, sxyz, kp, kw);
    k_gemm<<<(BB * N1) / 64, 256>>>(Wout, out);
    k_bn<<<(BB * COUT * N1) / 256, 256>>>(out, gamma, beta);
}